// round 6
// baseline (speedup 1.0000x reference)
#include <cuda_runtime.h>

// AngularSymmetry B=16, M=64.
//  prep (16 blocks x 1024): coalesced smem-transpose
//    S[b,j,k] = wgt*(g_jk+g_kj), g = __expf(-4 d^2)*dc
//    wgt = 0.125 (diag), 0.5 (cyclic dist 32), 1 otherwise; also zeroes out.
//  main (1024 blocks x 256): block = (b, i-pair, m-half). Two i-chains per
//    thread (ILP), 4 unrolled pair iters (+diag on h=0), Cody-Waite fast cos,
//    packed f32x2 powers/accumulators, atomicAdd combine across the 2 halves
//    (exactly 2 commutative adds onto 0 -> deterministic).

#define B_DIM 16
#define M_DIM 64

__device__ float S_buf[B_DIM * M_DIM * M_DIM];

__global__ __launch_bounds__(1024)
void prep_kernel(const float* __restrict__ d, const float* __restrict__ dc,
                 float* __restrict__ out)
{
    __shared__ float sg[M_DIM * 65];          // stride-65: conflict-free transpose
    const int b   = blockIdx.x;
    const int tid = threadIdx.x;              // 0..1023
    const float* db  = d  + b * 4096;
    const float* dcb = dc + b * 4096;

    if (tid < 384) out[b * 384 + tid] = 0.0f;     // zero 16*64*6 outputs total

    #pragma unroll
    for (int c = 0; c < 4; c++) {
        int e = tid + c * 1024;
        int j = e >> 6, k = e & 63;
        float dv = db[e];
        sg[j * 65 + k] = __expf(-4.0f * dv * dv) * dcb[e];
    }
    __syncthreads();

    #pragma unroll
    for (int c = 0; c < 4; c++) {
        int e = tid + c * 1024;
        int j = e >> 6, k = e & 63;
        int dd = (j - k) & 63;
        float w = (dd == 0) ? 0.125f : ((dd == 32) ? 0.5f : 1.0f);
        S_buf[b * 4096 + e] = w * (sg[j * 65 + k] + sg[k * 65 + j]);
    }
}

// ---- packed f32x2 helpers ----
typedef unsigned long long u64;
__device__ __forceinline__ u64 pack2(float lo, float hi) {
    u64 r; asm("mov.b64 %0, {%1, %2};" : "=l"(r) : "f"(lo), "f"(hi)); return r;
}
__device__ __forceinline__ void unpack2(u64 v, float& lo, float& hi) {
    asm("mov.b64 {%0, %1}, %2;" : "=f"(lo), "=f"(hi) : "l"(v));
}
__device__ __forceinline__ u64 mul2(u64 a, u64 b) {
    u64 r; asm("mul.rn.f32x2 %0, %1, %2;" : "=l"(r) : "l"(a), "l"(b)); return r;
}
__device__ __forceinline__ u64 add2(u64 a, u64 b) {
    u64 r; asm("add.rn.f32x2 %0, %1, %2;" : "=l"(r) : "l"(a), "l"(b)); return r;
}
__device__ __forceinline__ u64 fma2(u64 a, u64 b, u64 c) {
    u64 r; asm("fma.rn.f32x2 %0, %1, %2, %3;" : "=l"(r) : "l"(a), "l"(b), "l"(c)); return r;
}

// Fast cos: exact RNE(x/2pi) via magic-number fma, 2-word Cody-Waite
// reduction, MUFU cos. Phase error ~5e-7 rad up to |x|~4e6.
__device__ __forceinline__ float fast_cos(float x) {
    const float MAGIC = 12582912.0f;                 // 1.5 * 2^23
    float q = fmaf(x, 0.15915494309189535f, MAGIC) - MAGIC;
    float r = fmaf(q, -6.28318548202514648f, x);     // C1 = fp32(2*pi)
    r = fmaf(q, 1.74845553146599e-7f, r);            // C2 correction
    return __cosf(r);
}

__global__ __launch_bounds__(256, 6)
void angular_main(const float* __restrict__ dc,
                  const float* __restrict__ d,
                  const float* __restrict__ coords,
                  float* __restrict__ out)
{
    const int blk = blockIdx.x;        // 0..1023
    const int b   = blk >> 6;
    const int h   = blk & 1;           // m-half: 0 -> m 1..16 (+diag), 1 -> 17..32
    const int i0  = (blk & 62);        // i-pair base (even)
    const int i1  = i0 + 1;

    __shared__ float4 s_va[M_DIM], s_vb[M_DIM];   // {vx, vy, vz, d_ij}
    __shared__ float  s_Fa[M_DIM], s_Fb[M_DIM];   // dc_ij * exp(-4 d_ij^2)
    __shared__ float  s_S[M_DIM * M_DIM];         // 16 KB
    __shared__ u64    s_red[8][6];

    const int tid = threadIdx.x;

    // Preload S tile (coalesced float4, no math)
    {
        float4* sS4 = (float4*)s_S;
        const float4* gS4 = (const float4*)(S_buf + b * 4096);
        #pragma unroll
        for (int c = 0; c < 4; c++) {
            int p = tid + c * 256;
            sS4[p] = gS4[p];
        }
    }

    // i-row quantities for both i's (threads 0..127)
    if (tid < 128) {
        const int ii = (tid < 64) ? i0 : i1;
        const int j  = tid & 63;
        const float* cb = coords + (size_t)b * 192;
        float cx = cb[ii * 3 + 0];
        float cy = cb[ii * 3 + 1];
        float cz = cb[ii * 3 + 2];
        float4 v;
        v.x = cb[j * 3 + 0] - cx;
        v.y = cb[j * 3 + 1] - cy;
        v.z = cb[j * 3 + 2] - cz;
        v.w = d[(size_t)b * 4096 + ii * 64 + j];
        float F = dc[(size_t)b * 4096 + ii * 64 + j] * __expf(-4.0f * v.w * v.w);
        if (tid < 64) { s_va[j] = v; s_Fa[j] = F; }
        else          { s_vb[j] = v; s_Fb[j] = F; }
    }
    __syncthreads();

    const int k = tid & 63;
    const int g = tid >> 6;    // 0..3

    const float4 vka = s_va[k];
    const float4 vkb = s_vb[k];
    const float  Fka = s_Fa[k];
    const float  Fkb = s_Fb[k];

    const u64 ONE2 = 0x3F8000003F800000ull;  // (1.0f, 1.0f)
    u64 A2 = 0, A4 = 0, A8 = 0;              // i0: (lambda=+1, lambda=-1)
    u64 B2 = 0, B4 = 0, B8 = 0;              // i1

    const int mbase = (h << 4) + g + 1;      // m = mbase + 4t

    // t = 0..3: pair iters; t = 4 only on h == 0: diagonal (j = k)
    const int nit = 4 + (h == 0 ? 1 : 0);
    #pragma unroll 5
    for (int t = 0; t < nit; t++) {
        const int j = (t < 4) ? ((k + mbase + 4 * t) & 63) : k;

        const float Sv = s_S[(j << 6) + k];          // shared by both chains

        // ---- chain A (i0) ----
        float4 vja = s_va[j];
        float  Fja = s_Fa[j];
        float dotA = vja.x * vka.x + vja.y * vka.y + vja.z * vka.z;
        float denA = vja.w * vka.w + 1e-5f;
        float cA   = fast_cos(dotA / denA);
        float wA   = Fja * Sv;

        // ---- chain B (i1) ----
        float4 vjb = s_vb[j];
        float  Fjb = s_Fb[j];
        float dotB = vjb.x * vkb.x + vjb.y * vkb.y + vjb.z * vkb.z;
        float denB = vjb.w * vkb.w + 1e-5f;
        float cB   = fast_cos(dotB / denB);
        float wB   = Fjb * Sv;

        u64 ccA  = pack2(cA, __int_as_float(__float_as_int(cA) ^ 0x80000000));
        u64 tpmA = add2(ccA, ONE2);
        u64 t2A  = mul2(tpmA, tpmA);
        u64 t4A  = mul2(t2A, t2A);
        u64 t8A  = mul2(t4A, t4A);
        u64 wpA  = pack2(wA, wA);
        A2 = fma2(t2A, wpA, A2);
        A4 = fma2(t4A, wpA, A4);
        A8 = fma2(t8A, wpA, A8);

        u64 ccB  = pack2(cB, __int_as_float(__float_as_int(cB) ^ 0x80000000));
        u64 tpmB = add2(ccB, ONE2);
        u64 t2B  = mul2(tpmB, tpmB);
        u64 t4B  = mul2(t2B, t2B);
        u64 t8B  = mul2(t4B, t4B);
        u64 wpB  = pack2(wB, wB);
        B2 = fma2(t2B, wpB, B2);
        B4 = fma2(t4B, wpB, B4);
        B8 = fma2(t8B, wpB, B8);
    }

    // Apply hoisted Fk (packed) before reduction (Fk varies by k)
    {
        u64 Fpa = pack2(Fka, Fka);
        u64 Fpb = pack2(Fkb, Fkb);
        A2 = mul2(A2, Fpa); A4 = mul2(A4, Fpa); A8 = mul2(A8, Fpa);
        B2 = mul2(B2, Fpb); B4 = mul2(B4, Fpb); B8 = mul2(B8, Fpb);
    }

    // Packed warp reduction (64-bit shuffles + add.rn.f32x2)
    #pragma unroll
    for (int off = 16; off > 0; off >>= 1) {
        A2 = add2(A2, __shfl_down_sync(0xffffffffu, A2, off));
        A4 = add2(A4, __shfl_down_sync(0xffffffffu, A4, off));
        A8 = add2(A8, __shfl_down_sync(0xffffffffu, A8, off));
        B2 = add2(B2, __shfl_down_sync(0xffffffffu, B2, off));
        B4 = add2(B4, __shfl_down_sync(0xffffffffu, B4, off));
        B8 = add2(B8, __shfl_down_sync(0xffffffffu, B8, off));
    }

    const int wid  = tid >> 5;
    const int lane = tid & 31;
    if (lane == 0) {
        s_red[wid][0] = A2; s_red[wid][1] = A4; s_red[wid][2] = A8;
        s_red[wid][3] = B2; s_red[wid][4] = B4; s_red[wid][5] = B8;
    }
    __syncthreads();

    if (tid < 6) {
        u64 s = s_red[0][tid];
        #pragma unroll
        for (int w = 1; w < 8; w++) s = add2(s, s_red[w][tid]);
        float plus, minus;
        unpack2(s, plus, minus);
        const int ii = (tid < 3) ? i0 : i1;
        const int z  = (tid < 3) ? tid : tid - 3;     // zeta index 0..2
        const float scale = (z == 0) ? 0.5f : ((z == 1) ? 0.125f : 0.0078125f);
        float* o = out + ((size_t)b * 64 + ii) * 6;
        atomicAdd(&o[z],     plus  * scale);   // lambda = +1
        atomicAdd(&o[3 + z], minus * scale);   // lambda = -1
    }
}

extern "C" void kernel_launch(void* const* d_in, const int* in_sizes, int n_in,
                              void* d_out, int out_size)
{
    const float* d_cutoff = (const float*)d_in[0];
    const float* d        = (const float*)d_in[1];
    const float* coords   = (const float*)d_in[2];
    float* out = (float*)d_out;

    prep_kernel<<<B_DIM, 1024>>>(d, d_cutoff, out);
    angular_main<<<1024, 256>>>(d_cutoff, d, coords, out);
}

// round 7
// speedup vs baseline: 1.1571x; 1.1571x over previous
#include <cuda_runtime.h>

// AngularSymmetry B=16, M=64.
//  prep (16 blocks x 1024): coalesced smem-transpose, writes DIAGONAL-major
//    SD[b][m][k] = wgt * (g[(k+m)%64][k] + g[k][(k+m)%64]),  m = 0..32
//    g = __expf(-4 d^2) * dc ; wgt = 0.125 (m=0), 0.5 (m=32), 1 otherwise
//  main (1024 blocks x 256, one block per (b,i)): unordered pairs via cyclic
//    distance m = 4t+g+1 (t=0..7, group g=tid>>6) + diagonal (m=0, all groups).
//    SD read directly from global: uniform row m per warp, lane-consecutive k
//    -> fully coalesced, L2-resident, no smem tile, no preload.
//    Cody-Waite fast cos, packed f32x2 powers/accumulators/reduction.

#define B_DIM 16
#define M_DIM 64
#define SD_STRIDE (33 * 64)     // 2112 floats per batch

__device__ float SD_buf[B_DIM * SD_STRIDE];

__global__ __launch_bounds__(1024)
void prep_kernel(const float* __restrict__ d, const float* __restrict__ dc)
{
    __shared__ float sg[M_DIM * 65];          // stride-65: conflict-free transpose
    const int b   = blockIdx.x;
    const int tid = threadIdx.x;              // 0..1023
    const float* db  = d  + b * 4096;
    const float* dcb = dc + b * 4096;

    #pragma unroll
    for (int c = 0; c < 4; c++) {
        int e = tid + c * 1024;
        int j = e >> 6, k = e & 63;
        float dv = db[e];
        sg[j * 65 + k] = __expf(-4.0f * dv * dv) * dcb[e];
    }
    __syncthreads();

    #pragma unroll
    for (int c = 0; c < 3; c++) {
        int e = tid + c * 1024;
        if (e < SD_STRIDE) {
            int m = e >> 6, k = e & 63;
            int j = (k + m) & 63;
            float w = (m == 0) ? 0.125f : ((m == 32) ? 0.5f : 1.0f);
            SD_buf[b * SD_STRIDE + e] = w * (sg[j * 65 + k] + sg[k * 65 + j]);
        }
    }
}

// ---- packed f32x2 helpers ----
typedef unsigned long long u64;
__device__ __forceinline__ u64 pack2(float lo, float hi) {
    u64 r; asm("mov.b64 %0, {%1, %2};" : "=l"(r) : "f"(lo), "f"(hi)); return r;
}
__device__ __forceinline__ void unpack2(u64 v, float& lo, float& hi) {
    asm("mov.b64 {%0, %1}, %2;" : "=f"(lo), "=f"(hi) : "l"(v));
}
__device__ __forceinline__ u64 mul2(u64 a, u64 b) {
    u64 r; asm("mul.rn.f32x2 %0, %1, %2;" : "=l"(r) : "l"(a), "l"(b)); return r;
}
__device__ __forceinline__ u64 add2(u64 a, u64 b) {
    u64 r; asm("add.rn.f32x2 %0, %1, %2;" : "=l"(r) : "l"(a), "l"(b)); return r;
}
__device__ __forceinline__ u64 fma2(u64 a, u64 b, u64 c) {
    u64 r; asm("fma.rn.f32x2 %0, %1, %2, %3;" : "=l"(r) : "l"(a), "l"(b), "l"(c)); return r;
}

// Fast cos: exact RNE(x/2pi) via magic-number fma, 2-word Cody-Waite
// reduction, MUFU cos. Phase error ~5e-7 rad up to |x|~4e6.
__device__ __forceinline__ float fast_cos(float x) {
    const float MAGIC = 12582912.0f;                 // 1.5 * 2^23
    float q = fmaf(x, 0.15915494309189535f, MAGIC) - MAGIC;
    float r = fmaf(q, -6.28318548202514648f, x);     // C1 = fp32(2*pi)
    r = fmaf(q, 1.74845553146599e-7f, r);            // C2 correction
    return __cosf(r);
}

__global__ __launch_bounds__(256, 8)
void angular_main(const float* __restrict__ dc,
                  const float* __restrict__ d,
                  const float* __restrict__ coords,
                  float* __restrict__ out)
{
    const int bi = blockIdx.x;      // 0..1023
    const int b  = bi >> 6;
    const int i  = bi & 63;

    __shared__ float4 s_v4[M_DIM];          // {vx, vy, vz, d_ij}
    __shared__ float  s_F[M_DIM];           // dc_ij * exp(-4 d_ij^2)
    __shared__ u64    s_red[8][6];

    const int tid = threadIdx.x;

    // i-row quantities (threads 0..63); no S preload needed.
    if (tid < M_DIM) {
        const int j = tid;
        const float* cb = coords + (size_t)b * 192;
        float cx = cb[i * 3 + 0];
        float cy = cb[i * 3 + 1];
        float cz = cb[i * 3 + 2];
        float4 v;
        v.x = cb[j * 3 + 0] - cx;
        v.y = cb[j * 3 + 1] - cy;
        v.z = cb[j * 3 + 2] - cz;
        v.w = d[(size_t)b * 4096 + i * 64 + j];
        s_v4[j] = v;
        s_F[j]  = dc[(size_t)b * 4096 + i * 64 + j] * __expf(-4.0f * v.w * v.w);
    }
    __syncthreads();

    const int k = tid & 63;
    const int g = tid >> 6;    // 0..3

    const float4 vk = s_v4[k];
    const float  Fk = s_F[k];
    const float* SDb = SD_buf + b * SD_STRIDE;

    const u64 ONE2 = 0x3F8000003F800000ull;  // (1.0f, 1.0f)
    u64 acc2 = 0, acc4 = 0, acc8 = 0;        // (lambda=+1, lambda=-1) per zeta

    // t = 0..7: m = 4t+g+1 (pairs, m=1..32 across groups); t = 8: m = 0 (diag)
    #pragma unroll
    for (int t = 0; t < 9; t++) {
        const int m = (t < 8) ? (4 * t + g + 1) : 0;
        const int j = (k + m) & 63;

        float  Sv = SDb[(m << 6) + k];       // coalesced LDG, L2-resident
        float4 vj = s_v4[j];
        float  Fj = s_F[j];

        float dot = vj.x * vk.x + vj.y * vk.y + vj.z * vk.z;
        float den = vj.w * vk.w + 1e-5f;
        float c   = fast_cos(dot / den);     // IEEE div kept for tail accuracy
        float w   = Fj * Sv;                 // Fk applied after the loop

        u64 cc  = pack2(c, __int_as_float(__float_as_int(c) ^ 0x80000000));
        u64 tpm = add2(cc, ONE2);            // (1+c, 1-c)
        u64 t2  = mul2(tpm, tpm);
        u64 t4  = mul2(t2, t2);
        u64 t8  = mul2(t4, t4);
        u64 wp  = pack2(w, w);

        acc2 = fma2(t2, wp, acc2);
        acc4 = fma2(t4, wp, acc4);
        acc8 = fma2(t8, wp, acc8);
    }

    // Apply hoisted Fk (packed) before reduction (Fk varies by k)
    {
        u64 Fkp = pack2(Fk, Fk);
        acc2 = mul2(acc2, Fkp);
        acc4 = mul2(acc4, Fkp);
        acc8 = mul2(acc8, Fkp);
    }

    // Packed warp reduction (64-bit shuffles + add.rn.f32x2)
    #pragma unroll
    for (int off = 16; off > 0; off >>= 1) {
        acc2 = add2(acc2, __shfl_down_sync(0xffffffffu, acc2, off));
        acc4 = add2(acc4, __shfl_down_sync(0xffffffffu, acc4, off));
        acc8 = add2(acc8, __shfl_down_sync(0xffffffffu, acc8, off));
    }

    const int wid  = tid >> 5;
    const int lane = tid & 31;
    if (lane == 0) {
        s_red[wid][0] = acc2; s_red[wid][1] = acc4; s_red[wid][2] = acc8;
    }
    __syncthreads();

    if (tid < 3) {
        u64 s = s_red[0][tid];
        #pragma unroll
        for (int w = 1; w < 8; w++) s = add2(s, s_red[w][tid]);
        float plus, minus;
        unpack2(s, plus, minus);
        // scale = 2^(1 - zeta), zeta = [2,4,8]
        const float scale = (tid == 0) ? 0.5f : ((tid == 1) ? 0.125f : 0.0078125f);
        float* o = out + (size_t)bi * 6;
        o[tid]     = plus  * scale;   // lambda = +1
        o[3 + tid] = minus * scale;   // lambda = -1
    }
}

extern "C" void kernel_launch(void* const* d_in, const int* in_sizes, int n_in,
                              void* d_out, int out_size)
{
    const float* d_cutoff = (const float*)d_in[0];
    const float* d        = (const float*)d_in[1];
    const float* coords   = (const float*)d_in[2];
    float* out = (float*)d_out;

    prep_kernel<<<B_DIM, 1024>>>(d, d_cutoff);
    angular_main<<<1024, 256>>>(d_cutoff, d, coords, out);
}

// round 8
// speedup vs baseline: 1.3625x; 1.1775x over previous
#include <cuda_runtime.h>

// AngularSymmetry B=16, M=64.
//  prep (132 blocks x 256): direct per-element, fully parallel across SMs
//    SD[b][m][k] = wgt * (g[(k+m)%64][k] + g[k][(k+m)%64]),  m = 0..32
//    g = __expf(-4 d^2) * dc ; wgt = 0.125 (m=0), 0.5 (m=32), 1 otherwise
//  main (1024 blocks x 256, one block per (b,i)): unordered pairs via cyclic
//    distance m = 4t+g+1 (t=0..7, group g=tid>>6) + diagonal (m=0).
//    Launched with PDL (programmatic stream serialization): starts during
//    prep; cudaGridDependencySynchronize() fences before the first SD read.
//    Cody-Waite fast cos, packed f32x2 powers/accumulators/reduction.

#define B_DIM 16
#define M_DIM 64
#define SD_STRIDE (33 * 64)     // 2112 floats per batch
#define SD_TOTAL (B_DIM * SD_STRIDE)

__device__ float SD_buf[SD_TOTAL];

__global__ __launch_bounds__(256)
void prep_kernel(const float* __restrict__ d, const float* __restrict__ dc)
{
    const int e = blockIdx.x * 256 + threadIdx.x;
    if (e >= SD_TOTAL) return;
    const int b = e / SD_STRIDE;
    const int r = e - b * SD_STRIDE;
    const int m = r >> 6;
    const int k = r & 63;
    const int j = (k + m) & 63;

    const float* db  = d  + b * 4096;
    const float* dcb = dc + b * 4096;

    float djk = db[j * 64 + k];
    float dkj = db[k * 64 + j];
    float gjk = __expf(-4.0f * djk * djk) * dcb[j * 64 + k];
    float gkj = __expf(-4.0f * dkj * dkj) * dcb[k * 64 + j];

    const float w = (m == 0) ? 0.125f : ((m == 32) ? 0.5f : 1.0f);
    SD_buf[e] = w * (gjk + gkj);
}

// ---- packed f32x2 helpers ----
typedef unsigned long long u64;
__device__ __forceinline__ u64 pack2(float lo, float hi) {
    u64 r; asm("mov.b64 %0, {%1, %2};" : "=l"(r) : "f"(lo), "f"(hi)); return r;
}
__device__ __forceinline__ void unpack2(u64 v, float& lo, float& hi) {
    asm("mov.b64 {%0, %1}, %2;" : "=f"(lo), "=f"(hi) : "l"(v));
}
__device__ __forceinline__ u64 mul2(u64 a, u64 b) {
    u64 r; asm("mul.rn.f32x2 %0, %1, %2;" : "=l"(r) : "l"(a), "l"(b)); return r;
}
__device__ __forceinline__ u64 add2(u64 a, u64 b) {
    u64 r; asm("add.rn.f32x2 %0, %1, %2;" : "=l"(r) : "l"(a), "l"(b)); return r;
}
__device__ __forceinline__ u64 fma2(u64 a, u64 b, u64 c) {
    u64 r; asm("fma.rn.f32x2 %0, %1, %2, %3;" : "=l"(r) : "l"(a), "l"(b), "l"(c)); return r;
}

// Fast cos: exact RNE(x/2pi) via magic-number fma, 2-word Cody-Waite
// reduction, MUFU cos. Phase error ~5e-7 rad up to |x|~4e6.
__device__ __forceinline__ float fast_cos(float x) {
    const float MAGIC = 12582912.0f;                 // 1.5 * 2^23
    float q = fmaf(x, 0.15915494309189535f, MAGIC) - MAGIC;
    float r = fmaf(q, -6.28318548202514648f, x);     // C1 = fp32(2*pi)
    r = fmaf(q, 1.74845553146599e-7f, r);            // C2 correction
    return __cosf(r);
}

__global__ __launch_bounds__(256, 8)
void angular_main(const float* __restrict__ dc,
                  const float* __restrict__ d,
                  const float* __restrict__ coords,
                  float* __restrict__ out)
{
    const int bi = blockIdx.x;      // 0..1023
    const int b  = bi >> 6;
    const int i  = bi & 63;

    __shared__ float4 s_v4[M_DIM];          // {vx, vy, vz, d_ij}
    __shared__ float  s_F[M_DIM];           // dc_ij * exp(-4 d_ij^2)
    __shared__ u64    s_red[8][6];

    const int tid = threadIdx.x;

    // Prologue: only harness inputs (safe before prep completes under PDL).
    if (tid < M_DIM) {
        const int j = tid;
        const float* cb = coords + (size_t)b * 192;
        float cx = cb[i * 3 + 0];
        float cy = cb[i * 3 + 1];
        float cz = cb[i * 3 + 2];
        float4 v;
        v.x = cb[j * 3 + 0] - cx;
        v.y = cb[j * 3 + 1] - cy;
        v.z = cb[j * 3 + 2] - cz;
        v.w = d[(size_t)b * 4096 + i * 64 + j];
        s_v4[j] = v;
        s_F[j]  = dc[(size_t)b * 4096 + i * 64 + j] * __expf(-4.0f * v.w * v.w);
    }
    __syncthreads();

    // PDL fence: prep's SD_buf writes must be visible past this point.
    cudaGridDependencySynchronize();

    const int k = tid & 63;
    const int g = tid >> 6;    // 0..3

    const float4 vk = s_v4[k];
    const float  Fk = s_F[k];
    const float* SDb = SD_buf + b * SD_STRIDE;

    const u64 ONE2 = 0x3F8000003F800000ull;  // (1.0f, 1.0f)
    u64 acc2 = 0, acc4 = 0, acc8 = 0;        // (lambda=+1, lambda=-1) per zeta

    // t = 0..7: m = 4t+g+1 (pairs, m=1..32 across groups); t = 8: m = 0 (diag)
    #pragma unroll
    for (int t = 0; t < 9; t++) {
        const int m = (t < 8) ? (4 * t + g + 1) : 0;
        const int j = (k + m) & 63;

        float  Sv = SDb[(m << 6) + k];       // coalesced LDG, L2-resident
        float4 vj = s_v4[j];
        float  Fj = s_F[j];

        float dot = vj.x * vk.x + vj.y * vk.y + vj.z * vk.z;
        float den = vj.w * vk.w + 1e-5f;
        float c   = fast_cos(dot / den);     // IEEE div kept for tail accuracy
        float w   = Fj * Sv;                 // Fk applied after the loop

        u64 cc  = pack2(c, __int_as_float(__float_as_int(c) ^ 0x80000000));
        u64 tpm = add2(cc, ONE2);            // (1+c, 1-c)
        u64 t2  = mul2(tpm, tpm);
        u64 t4  = mul2(t2, t2);
        u64 t8  = mul2(t4, t4);
        u64 wp  = pack2(w, w);

        acc2 = fma2(t2, wp, acc2);
        acc4 = fma2(t4, wp, acc4);
        acc8 = fma2(t8, wp, acc8);
    }

    // Apply hoisted Fk (packed) before reduction (Fk varies by k)
    {
        u64 Fkp = pack2(Fk, Fk);
        acc2 = mul2(acc2, Fkp);
        acc4 = mul2(acc4, Fkp);
        acc8 = mul2(acc8, Fkp);
    }

    // Packed warp reduction (64-bit shuffles + add.rn.f32x2)
    #pragma unroll
    for (int off = 16; off > 0; off >>= 1) {
        acc2 = add2(acc2, __shfl_down_sync(0xffffffffu, acc2, off));
        acc4 = add2(acc4, __shfl_down_sync(0xffffffffu, acc4, off));
        acc8 = add2(acc8, __shfl_down_sync(0xffffffffu, acc8, off));
    }

    const int wid  = tid >> 5;
    const int lane = tid & 31;
    if (lane == 0) {
        s_red[wid][0] = acc2; s_red[wid][1] = acc4; s_red[wid][2] = acc8;
    }
    __syncthreads();

    if (tid < 3) {
        u64 s = s_red[0][tid];
        #pragma unroll
        for (int w = 1; w < 8; w++) s = add2(s, s_red[w][tid]);
        float plus, minus;
        unpack2(s, plus, minus);
        // scale = 2^(1 - zeta), zeta = [2,4,8]
        const float scale = (tid == 0) ? 0.5f : ((tid == 1) ? 0.125f : 0.0078125f);
        float* o = out + (size_t)bi * 6;
        o[tid]     = plus  * scale;   // lambda = +1
        o[3 + tid] = minus * scale;   // lambda = -1
    }
}

extern "C" void kernel_launch(void* const* d_in, const int* in_sizes, int n_in,
                              void* d_out, int out_size)
{
    const float* d_cutoff = (const float*)d_in[0];
    const float* d        = (const float*)d_in[1];
    const float* coords   = (const float*)d_in[2];
    float* out = (float*)d_out;

    prep_kernel<<<(SD_TOTAL + 255) / 256, 256>>>(d, d_cutoff);

    // Main launched with programmatic stream serialization (PDL): may start
    // while prep is still in flight; the grid-dependency sync inside the
    // kernel orders SD_buf reads after prep completion.
    cudaLaunchConfig_t cfg = {};
    cfg.gridDim  = dim3(1024, 1, 1);
    cfg.blockDim = dim3(256, 1, 1);
    cfg.dynamicSmemBytes = 0;
    cfg.stream = 0;
    cudaLaunchAttribute attr[1];
    attr[0].id = cudaLaunchAttributeProgrammaticStreamSerialization;
    attr[0].val.programmaticStreamSerializationAllowed = 1;
    cfg.attrs = attr;
    cfg.numAttrs = 1;
    cudaLaunchKernelEx(&cfg, angular_main, d_cutoff, d, coords, out);
}

// round 9
// speedup vs baseline: 1.3659x; 1.0025x over previous
#include <cuda_runtime.h>

// AngularSymmetry B=16, M=64.
//  prep (132 blocks x 256): SD[b][m][k] = wgt*(g[(k+m)%64][k] + g[k][(k+m)%64]),
//    m=0..32; g = __expf(-4 d^2)*dc; wgt = 0.125 (m=0), 0.5 (m=32), 1 else.
//  main (1024 blocks x 256, PDL-overlapped with prep): block=(b,i).
//    Pair enumeration m = 4t+g+1 (t=0..7, group g=tid>>6); diagonal handled
//    by g==0 warps only (SD row 0 scaled x4).
//    Smem arrays replicated to 128 entries -> j = k+m unmasked, all loop
//    addresses become [base + immediate] after full unroll (no per-iter ALU).
//    Cody-Waite fast cos, packed f32x2 powers/accumulators/reduction.

#define B_DIM 16
#define M_DIM 64
#define SD_STRIDE (33 * 64)     // 2112 floats per batch
#define SD_TOTAL (B_DIM * SD_STRIDE)

__device__ float SD_buf[SD_TOTAL];

__global__ __launch_bounds__(256)
void prep_kernel(const float* __restrict__ d, const float* __restrict__ dc)
{
    const int e = blockIdx.x * 256 + threadIdx.x;
    if (e >= SD_TOTAL) return;
    const int b = e / SD_STRIDE;
    const int r = e - b * SD_STRIDE;
    const int m = r >> 6;
    const int k = r & 63;
    const int j = (k + m) & 63;

    const float* db  = d  + b * 4096;
    const float* dcb = dc + b * 4096;

    float djk = db[j * 64 + k];
    float dkj = db[k * 64 + j];
    float gjk = __expf(-4.0f * djk * djk) * dcb[j * 64 + k];
    float gkj = __expf(-4.0f * dkj * dkj) * dcb[k * 64 + j];

    const float w = (m == 0) ? 0.125f : ((m == 32) ? 0.5f : 1.0f);
    SD_buf[e] = w * (gjk + gkj);
}

// ---- packed f32x2 helpers ----
typedef unsigned long long u64;
__device__ __forceinline__ u64 pack2(float lo, float hi) {
    u64 r; asm("mov.b64 %0, {%1, %2};" : "=l"(r) : "f"(lo), "f"(hi)); return r;
}
__device__ __forceinline__ void unpack2(u64 v, float& lo, float& hi) {
    asm("mov.b64 {%0, %1}, %2;" : "=f"(lo), "=f"(hi) : "l"(v));
}
__device__ __forceinline__ u64 mul2(u64 a, u64 b) {
    u64 r; asm("mul.rn.f32x2 %0, %1, %2;" : "=l"(r) : "l"(a), "l"(b)); return r;
}
__device__ __forceinline__ u64 add2(u64 a, u64 b) {
    u64 r; asm("add.rn.f32x2 %0, %1, %2;" : "=l"(r) : "l"(a), "l"(b)); return r;
}
__device__ __forceinline__ u64 fma2(u64 a, u64 b, u64 c) {
    u64 r; asm("fma.rn.f32x2 %0, %1, %2, %3;" : "=l"(r) : "l"(a), "l"(b), "l"(c)); return r;
}

// Fast cos: exact RNE(x/2pi) via magic-number fma, 2-word Cody-Waite
// reduction, MUFU cos. Phase error ~5e-7 rad up to |x|~4e6.
__device__ __forceinline__ float fast_cos(float x) {
    const float MAGIC = 12582912.0f;                 // 1.5 * 2^23
    float q = fmaf(x, 0.15915494309189535f, MAGIC) - MAGIC;
    float r = fmaf(q, -6.28318548202514648f, x);     // C1 = fp32(2*pi)
    r = fmaf(q, 1.74845553146599e-7f, r);            // C2 correction
    return __cosf(r);
}

__global__ __launch_bounds__(256, 7)
void angular_main(const float* __restrict__ dc,
                  const float* __restrict__ d,
                  const float* __restrict__ coords,
                  float* __restrict__ out)
{
    const int bi = blockIdx.x;      // 0..1023
    const int b  = bi >> 6;
    const int i  = bi & 63;

    __shared__ float4 s_v4[2 * M_DIM];      // replicated: [j] == [j+64]
    __shared__ float  s_F[2 * M_DIM];       // replicated
    __shared__ u64    s_red[8][3];

    const int tid = threadIdx.x;

    // Prologue: only harness inputs (safe before prep completes under PDL).
    // Threads 0..127 build both replicas (tid>>6 selects the copy).
    if (tid < 128) {
        const int j = tid & 63;
        const float* cb = coords + (size_t)b * 192;
        float cx = cb[i * 3 + 0];
        float cy = cb[i * 3 + 1];
        float cz = cb[i * 3 + 2];
        float4 v;
        v.x = cb[j * 3 + 0] - cx;
        v.y = cb[j * 3 + 1] - cy;
        v.z = cb[j * 3 + 2] - cz;
        v.w = d[(size_t)b * 4096 + i * 64 + j];
        float F = dc[(size_t)b * 4096 + i * 64 + j] * __expf(-4.0f * v.w * v.w);
        s_v4[tid] = v;          // tid = copy*64 + j
        s_F[tid]  = F;
    }
    __syncthreads();

    // PDL fence: prep's SD_buf writes must be visible past this point.
    cudaGridDependencySynchronize();

    const int k = tid & 63;
    const int g = tid >> 6;    // 0..3

    const float4 vk = s_v4[k];
    const float  Fk = s_F[k];
    // Bases for immediate-offset addressing: iteration t uses index base + 4t.
    const float4* vbase = s_v4 + (k + g + 1);     // j = k+g+1+4t  (max 95 < 128)
    const float*  fbase = s_F  + (k + g + 1);
    const float*  sbase = SD_buf + b * SD_STRIDE + ((g + 1) << 6) + k;  // +256*t

    const u64 ONE2 = 0x3F8000003F800000ull;  // (1.0f, 1.0f)
    u64 acc2 = 0, acc4 = 0, acc8 = 0;        // (lambda=+1, lambda=-1) per zeta

    // 8 pair iterations: m = 4t+g+1 covers m = 1..32 across the 4 groups.
    #pragma unroll
    for (int t = 0; t < 8; t++) {
        float  Sv = sbase[t << 8];           // LDG [base + 1024*t], coalesced
        float4 vj = vbase[t << 2];           // LDS.128 [base + 64*t]
        float  Fj = fbase[t << 2];           // LDS.32  [base + 16*t]

        float dot = vj.x * vk.x + vj.y * vk.y + vj.z * vk.z;
        float den = vj.w * vk.w + 1e-5f;
        float c   = fast_cos(dot / den);     // IEEE div kept for tail accuracy
        float w   = Fj * Sv;                 // Fk applied after the loop

        u64 cc  = pack2(c, __int_as_float(__float_as_int(c) ^ 0x80000000));
        u64 tpm = add2(cc, ONE2);            // (1+c, 1-c)
        u64 t2  = mul2(tpm, tpm);
        u64 t4  = mul2(t2, t2);
        u64 t8  = mul2(t4, t4);
        u64 wp  = pack2(w, w);

        acc2 = fma2(t2, wp, acc2);
        acc4 = fma2(t4, wp, acc4);
        acc8 = fma2(t8, wp, acc8);
    }

    // Diagonal (j == k): g==0 warps only, weight x4 (SD row 0 carries 0.125;
    // 0.5*(2 g_kk) = exactly one ordered term). Warp-uniform branch.
    if (g == 0) {
        float  Sv = 4.0f * SD_buf[b * SD_STRIDE + k];
        float dot = vk.x * vk.x + vk.y * vk.y + vk.z * vk.z;
        float den = vk.w * vk.w + 1e-5f;
        float c   = fast_cos(dot / den);
        float w   = Fk * Sv;                 // Fj == Fk on the diagonal

        u64 cc  = pack2(c, __int_as_float(__float_as_int(c) ^ 0x80000000));
        u64 tpm = add2(cc, ONE2);
        u64 t2  = mul2(tpm, tpm);
        u64 t4  = mul2(t2, t2);
        u64 t8  = mul2(t4, t4);
        u64 wp  = pack2(w, w);

        acc2 = fma2(t2, wp, acc2);
        acc4 = fma2(t4, wp, acc4);
        acc8 = fma2(t8, wp, acc8);
    }

    // Apply hoisted Fk (packed) before reduction (Fk varies by k)
    {
        u64 Fkp = pack2(Fk, Fk);
        acc2 = mul2(acc2, Fkp);
        acc4 = mul2(acc4, Fkp);
        acc8 = mul2(acc8, Fkp);
    }

    // Packed warp reduction (64-bit shuffles + add.rn.f32x2)
    #pragma unroll
    for (int off = 16; off > 0; off >>= 1) {
        acc2 = add2(acc2, __shfl_down_sync(0xffffffffu, acc2, off));
        acc4 = add2(acc4, __shfl_down_sync(0xffffffffu, acc4, off));
        acc8 = add2(acc8, __shfl_down_sync(0xffffffffu, acc8, off));
    }

    const int wid  = tid >> 5;
    const int lane = tid & 31;
    if (lane == 0) {
        s_red[wid][0] = acc2; s_red[wid][1] = acc4; s_red[wid][2] = acc8;
    }
    __syncthreads();

    if (tid < 3) {
        u64 s = s_red[0][tid];
        #pragma unroll
        for (int w = 1; w < 8; w++) s = add2(s, s_red[w][tid]);
        float plus, minus;
        unpack2(s, plus, minus);
        // scale = 2^(1 - zeta), zeta = [2,4,8]
        const float scale = (tid == 0) ? 0.5f : ((tid == 1) ? 0.125f : 0.0078125f);
        float* o = out + (size_t)bi * 6;
        o[tid]     = plus  * scale;   // lambda = +1
        o[3 + tid] = minus * scale;   // lambda = -1
    }
}

extern "C" void kernel_launch(void* const* d_in, const int* in_sizes, int n_in,
                              void* d_out, int out_size)
{
    const float* d_cutoff = (const float*)d_in[0];
    const float* d        = (const float*)d_in[1];
    const float* coords   = (const float*)d_in[2];
    float* out = (float*)d_out;

    prep_kernel<<<(SD_TOTAL + 255) / 256, 256>>>(d, d_cutoff);

    // Main launched with programmatic stream serialization (PDL): may start
    // while prep is still in flight; the grid-dependency sync inside the
    // kernel orders SD_buf reads after prep completion.
    cudaLaunchConfig_t cfg = {};
    cfg.gridDim  = dim3(1024, 1, 1);
    cfg.blockDim = dim3(256, 1, 1);
    cfg.dynamicSmemBytes = 0;
    cfg.stream = 0;
    cudaLaunchAttribute attr[1];
    attr[0].id = cudaLaunchAttributeProgrammaticStreamSerialization;
    attr[0].val.programmaticStreamSerializationAllowed = 1;
    cfg.attrs = attr;
    cfg.numAttrs = 1;
    cudaLaunchKernelEx(&cfg, angular_main, d_cutoff, d, coords, out);
}